// round 12
// baseline (speedup 1.0000x reference)
#include <cuda_runtime.h>

#define BB 64
#define HH 56
#define WW 56
#define CC 256
#define COUT 64
#define ROUTES 4
#define RW (CC / ROUTES)          // 64 channels per route
#define RCHUNKS 14                // 4 rows per chunk
#define SLOTS 9                   // 3x3 (dh,dw) classes
#define NQ (SLOTS * CC / 4)       // 576 float4 quads per batch image sum
#define W2N (SLOTS * CC * ROUTES) // 9216 composed weights

// per-(batch,chunk) partial patch sums: [BB][RCHUNKS][SLOTS][CC] floats (~8 MB)
__device__ float g_S2[BB * RCHUNKS * SLOTS * CC];
// per-batch private copies of composed weights W2 = (conv_w @ fc_w)/729
__device__ float g_W2b[BB * W2N];
__device__ int   g_cnt[BB];            // patch completion counters (self-reset)
__device__ volatile int g_w2done[BB];  // per-batch W2-ready flags (self-reset)
__device__ int   g_route[BB];

__device__ __forceinline__ float4 f4add(float4 a, float4 b) {
    return make_float4(a.x + b.x, a.y + b.y, a.z + b.z, a.w + b.w);
}
__device__ __forceinline__ float4 f4sub(float4 a, float4 b) {
    return make_float4(a.x - b.x, a.y - b.y, a.z - b.z, a.w - b.w);
}
__device__ __forceinline__ float4 f4fma(float s, float4 w, float4 acc) {
    return make_float4(fmaf(s, w.x, acc.x), fmaf(s, w.y, acc.y),
                       fmaf(s, w.z, acc.z), fmaf(s, w.w, acc.w));
}

// ---------------------------------------------------------------------------
// K1: ONE kernel, grid (15, BB), x = slot (batch-contiguous bids).
//  slot 0:      compute this batch's PRIVATE full W2 copy (conv_w L2-shared),
//               publish g_w2done[b]. Runs before the batch's patch blocks.
//  slots 1..14: patch chunk = slot-1 (stream 4 rows -> 9-slot partial).
//               LAST patch block of the batch (atomic counter): spin (trivially
//               short) on g_w2done[b], then logits = S . W2 + c, argmax ->
//               g_route[b] + out_logits. Tail is cheap (L2 reads + 9K FMA).
// ---------------------------------------------------------------------------
__global__ __launch_bounds__(256) void patch_route_kernel(const float* __restrict__ in,
                                                          const float* __restrict__ conv_w,
                                                          const float* __restrict__ conv_b,
                                                          const float* __restrict__ fc_w,
                                                          const float* __restrict__ fc_b,
                                                          float* __restrict__ out_logits) {
    const int slot = blockIdx.x;           // 0..14
    const int b    = blockIdx.y;           // 0..63
    const int tid  = threadIdx.x;

    if (slot == 0) {
        // ---- private W2 copy for batch b ------------------------------------
        __shared__ float sfc[COUT * ROUTES];
        if (tid < COUT * ROUTES) sfc[tid] = fc_w[tid];
        __syncthreads();

        float* W2 = g_W2b + (size_t)b * W2N;
#pragma unroll
        for (int k = 0; k < W2N / 256; k++) {       // 36 outputs per thread
            const int idx = tid + k * 256;
            const int i   = idx >> 2;
            const int r   = idx & 3;
            float s = 0.f;
#pragma unroll 16
            for (int o = 0; o < COUT; o++)
                s = fmaf(conv_w[(size_t)i * COUT + o], sfc[o * ROUTES + r], s);
            W2[idx] = s * (1.0f / 729.0f);
        }
        __syncthreads();
        if (tid == 0) {
            __threadfence();                        // publish W2 stores
            g_w2done[b] = 1;
        }
        return;
    }

    // ================= patch streaming =================
    const int chunk = slot - 1;
    const int q     = tid & 63;            // channel quad 0..63
    const int rt    = tid >> 6;            // row-thread 0..3
    const int h     = chunk * 4 + rt;

    const float4* row = (const float4*)in
                      + ((size_t)(b * HH + h) * WW) * (CC / 4) + q;

    float4 e = make_float4(0.f, 0.f, 0.f, 0.f);
    float4 o = make_float4(0.f, 0.f, 0.f, 0.f);
    float4 v0, v54, v55;
#pragma unroll
    for (int w = 0; w < WW; w += 2) {
        float4 a  = row[(size_t)w * (CC / 4)];
        float4 bb = row[(size_t)(w + 1) * (CC / 4)];
        if (w == 0)  { v0 = a; }
        if (w == 54) { v54 = a; v55 = bb; }
        e = f4add(e, a);
        o = f4add(o, bb);
    }

    __shared__ float4 sacc[4][3][64];
    sacc[rt][0][q] = f4sub(e, v54);  // W0: even w in [0,52]
    sacc[rt][1][q] = f4sub(o, v55);  // W1: odd  w in [1,53]
    sacc[rt][2][q] = f4sub(e, v0);   // W2: even w in [2,54]
    __syncthreads();

    if (rt == 0) {
        float4 outv[SLOTS];
#pragma unroll
        for (int s = 0; s < SLOTS; s++) outv[s] = make_float4(0.f, 0.f, 0.f, 0.f);

#pragma unroll
        for (int r = 0; r < 4; r++) {
            const int hh = chunk * 4 + r;
            const float4 W0 = sacc[r][0][q];
            const float4 W1 = sacc[r][1][q];
            const float4 W2 = sacc[r][2][q];
            if ((hh & 1) == 0) {
                if (hh <= 52) { outv[0] = f4add(outv[0], W0); outv[1] = f4add(outv[1], W1); outv[2] = f4add(outv[2], W2); }
                if (hh >= 2)  { outv[6] = f4add(outv[6], W0); outv[7] = f4add(outv[7], W1); outv[8] = f4add(outv[8], W2); }
            } else {
                if (hh <= 53) { outv[3] = f4add(outv[3], W0); outv[4] = f4add(outv[4], W1); outv[5] = f4add(outv[5], W2); }
            }
        }

        float4* dst = (float4*)g_S2 + ((size_t)(b * RCHUNKS + chunk) * SLOTS) * (CC / 4) + q;
#pragma unroll
        for (int s = 0; s < SLOTS; s++)
            dst[(size_t)s * (CC / 4)] = outv[s];
    }
    __syncthreads();

    // ---- per-batch completion counter; only last block runs the tail -------
    __shared__ int s_last;
    if (tid == 0) {
        __threadfence();                            // publish g_S2 stores
        int old = atomicAdd(&g_cnt[b], 1);
        s_last = (old == RCHUNKS - 1);
        if (s_last) g_cnt[b] = 0;                   // reset for next replay
    }
    __syncthreads();
    if (!s_last) return;

    // ================= routing tail =================
    if (tid == 0) {
        while (g_w2done[b] == 0) { __nanosleep(64); }  // nearly always ready
        g_w2done[b] = 0;                               // reset for next replay
        __threadfence();                               // acquire W2 + g_S2
    }
    __syncthreads();

    const float* W2 = g_W2b + (size_t)b * W2N;

    float4 acc = make_float4(0.f, 0.f, 0.f, 0.f);
    for (int q4 = tid; q4 < NQ; q4 += 256) {
        float4 s = make_float4(0.f, 0.f, 0.f, 0.f);
#pragma unroll
        for (int k = 0; k < RCHUNKS; k++) {
            const float4* src = (const float4*)g_S2
                              + (size_t)(b * RCHUNKS + k) * NQ + q4;
            s = f4add(s, __ldcg(src));
        }
        const float4* w2 = (const float4*)W2 + q4 * 4;  // rows i=4q4..4q4+3
        acc = f4fma(s.x, w2[0], acc);
        acc = f4fma(s.y, w2[1], acc);
        acc = f4fma(s.z, w2[2], acc);
        acc = f4fma(s.w, w2[3], acc);
    }

#pragma unroll
    for (int off = 16; off > 0; off >>= 1) {
        acc.x += __shfl_xor_sync(0xFFFFFFFFu, acc.x, off);
        acc.y += __shfl_xor_sync(0xFFFFFFFFu, acc.y, off);
        acc.z += __shfl_xor_sync(0xFFFFFFFFu, acc.z, off);
        acc.w += __shfl_xor_sync(0xFFFFFFFFu, acc.w, off);
    }

    __shared__ float4 wred[8];
    if ((tid & 31) == 0) wred[tid >> 5] = acc;
    __syncthreads();

    if (tid == 0) {
        float4 tot = wred[0];
#pragma unroll
        for (int wg = 1; wg < 8; wg++) tot = f4add(tot, wred[wg]);

        float l[ROUTES] = {tot.x, tot.y, tot.z, tot.w};
#pragma unroll
        for (int r = 0; r < ROUTES; r++) {
            float c = fc_b[r];
            for (int o2 = 0; o2 < COUT; o2++)
                c = fmaf(conv_b[o2], fc_w[o2 * ROUTES + r], c);
            l[r] += c;
        }

        float best = l[0];
        int br = 0;
#pragma unroll
        for (int r = 1; r < ROUTES; r++)
            if (l[r] > best) { best = l[r]; br = r; }   // first-max == argmax
        g_route[b] = br;

#pragma unroll
        for (int r = 0; r < ROUTES; r++)
            out_logits[b * ROUTES + r] = l[r];
    }
}

// ---------------------------------------------------------------------------
// K3: routed channel-group gather (measured-best config, at its traffic floor).
// Block = (batch, 64-pixel tile), 4 independent float4 copies per thread.
// ---------------------------------------------------------------------------
__global__ __launch_bounds__(256) void gather_kernel(const float4* __restrict__ in4,
                                                     float4* __restrict__ out4) {
    const int b = blockIdx.x;
    const int r = g_route[b];
    const size_t base_pix = (size_t)b * (HH * WW) + (size_t)blockIdx.y * 64;
    const float4* src = in4 + base_pix * (CC / 4) + r * (RW / 4);
    float4* dst = out4 + base_pix * (RW / 4);

    const int t = threadIdx.x;
#pragma unroll
    for (int k = 0; k < 4; k++) {
        const int item = t + k * 256;      // 0..1023 = 64 pixels x 16 float4
        const int p = item >> 4;
        const int j = item & 15;
        dst[item] = src[(size_t)p * (CC / 4) + j];
    }
}

// ---------------------------------------------------------------------------
extern "C" void kernel_launch(void* const* d_in, const int* in_sizes, int n_in,
                              void* d_out, int out_size) {
    const float* in     = (const float*)d_in[0];
    const float* conv_w = (const float*)d_in[1];
    const float* conv_b = (const float*)d_in[2];
    const float* fc_w   = (const float*)d_in[3];
    const float* fc_b   = (const float*)d_in[4];

    float* out        = (float*)d_out;
    float* out_logits = out + (size_t)BB * HH * WW * RW;  // x first, then logits

    patch_route_kernel<<<dim3(RCHUNKS + 1, BB), 256>>>(in, conv_w, conv_b, fc_w, fc_b,
                                                       out_logits);
    gather_kernel<<<dim3(BB, HH * WW / 64), 256>>>((const float4*)in, (float4*)out);
}

// round 13
// speedup vs baseline: 3.3869x; 3.3869x over previous
#include <cuda_runtime.h>

#define BB 64
#define HH 56
#define WW 56
#define CC 256
#define COUT 64
#define ROUTES 4
#define RW (CC / ROUTES)          // 64 channels per route
#define RCHUNKS 14                // 4 rows per chunk
#define SLOTS 9                   // 3x3 (dh,dw) classes
#define NQ (SLOTS * CC / 4)       // 576 float4 quads per batch image sum

// per-(batch,chunk) partial patch sums: [BB][RCHUNKS][SLOTS][CC] floats (~8 MB)
__device__ float g_S2[BB * RCHUNKS * SLOTS * CC];
// composed routing weights: W2[i][r] = (conv_w @ fc_w)[i][r] / 729   (2304 x 4)
__device__ float g_W2[SLOTS * CC * ROUTES];
__device__ float g_C[ROUTES];     // c[r] = conv_b @ fc_w + fc_b
__device__ int   g_route[BB];

__device__ __forceinline__ float4 f4add(float4 a, float4 b) {
    return make_float4(a.x + b.x, a.y + b.y, a.z + b.z, a.w + b.w);
}
__device__ __forceinline__ float4 f4sub(float4 a, float4 b) {
    return make_float4(a.x - b.x, a.y - b.y, a.z - b.z, a.w - b.w);
}
__device__ __forceinline__ float4 f4fma(float s, float4 w, float4 acc) {
    return make_float4(fmaf(s, w.x, acc.x), fmaf(s, w.y, acc.y),
                       fmaf(s, w.z, acc.z), fmaf(s, w.w, acc.w));
}

// ---------------------------------------------------------------------------
// K1: streaming patch-sum reduction (grid y >= 1, chunk = y-1) + piggybacked
// W2 composition (grid y == 0 -> FIRST 64 bids, hidden under the stream;
// in R11 these ran last and serialized a ~2-3us tail before K2).
// Patch block = (batch, 4-row chunk), 256 threads = 64 channel-quads x 4 rows.
// Per row: even/odd running float4 sums + edge captures -> 3 dw-class sums;
// reducer (rt==0) applies h-parity/boundary logic, stores 9 slots to scratch.
// ---------------------------------------------------------------------------
__global__ __launch_bounds__(256) void patch_w2_kernel(const float* __restrict__ in,
                                                       const float* __restrict__ conv_w,
                                                       const float* __restrict__ conv_b,
                                                       const float* __restrict__ fc_w,
                                                       const float* __restrict__ fc_b) {
    const int b   = blockIdx.x;
    const int yy  = blockIdx.y;            // 0 = W2 strip, 1..14 = patch chunks
    const int tid = threadIdx.x;

    if (yy == 0) {
        // ---- W2 strip: rows [b*36, (b+1)*36), 4 routes each -----------------
        if (tid < 144) {
            const int i = b * 36 + (tid >> 2);
            const int r = tid & 3;
            float s = 0.f;
#pragma unroll 16
            for (int o = 0; o < COUT; o++)
                s = fmaf(conv_w[(size_t)i * COUT + o], fc_w[o * ROUTES + r], s);
            g_W2[i * ROUTES + r] = s * (1.0f / 729.0f);
        } else if (b == 0 && tid >= 160 && tid < 160 + ROUTES) {
            const int r = tid - 160;
            float s = fc_b[r];
            for (int o = 0; o < COUT; o++)
                s = fmaf(conv_b[o], fc_w[o * ROUTES + r], s);
            g_C[r] = s;
        }
        return;
    }

    const int chunk = yy - 1;
    const int q  = tid & 63;               // channel quad 0..63
    const int rt = tid >> 6;               // row-thread 0..3
    const int h  = chunk * 4 + rt;

    const float4* row = (const float4*)in
                      + ((size_t)(b * HH + h) * WW) * (CC / 4) + q;

    float4 e = make_float4(0.f, 0.f, 0.f, 0.f);
    float4 o = make_float4(0.f, 0.f, 0.f, 0.f);
    float4 v0, v54, v55;
#pragma unroll
    for (int w = 0; w < WW; w += 2) {
        float4 a  = row[(size_t)w * (CC / 4)];
        float4 bb = row[(size_t)(w + 1) * (CC / 4)];
        if (w == 0)  { v0 = a; }
        if (w == 54) { v54 = a; v55 = bb; }
        e = f4add(e, a);
        o = f4add(o, bb);
    }

    __shared__ float4 sacc[4][3][64];
    sacc[rt][0][q] = f4sub(e, v54);  // W0: even w in [0,52]
    sacc[rt][1][q] = f4sub(o, v55);  // W1: odd  w in [1,53]
    sacc[rt][2][q] = f4sub(e, v0);   // W2: even w in [2,54]
    __syncthreads();

    if (rt == 0) {
        float4 outv[SLOTS];
#pragma unroll
        for (int s = 0; s < SLOTS; s++) outv[s] = make_float4(0.f, 0.f, 0.f, 0.f);

#pragma unroll
        for (int r = 0; r < 4; r++) {
            const int hh = chunk * 4 + r;
            const float4 W0 = sacc[r][0][q];
            const float4 W1 = sacc[r][1][q];
            const float4 W2 = sacc[r][2][q];
            if ((hh & 1) == 0) {
                if (hh <= 52) { outv[0] = f4add(outv[0], W0); outv[1] = f4add(outv[1], W1); outv[2] = f4add(outv[2], W2); }
                if (hh >= 2)  { outv[6] = f4add(outv[6], W0); outv[7] = f4add(outv[7], W1); outv[8] = f4add(outv[8], W2); }
            } else {
                if (hh <= 53) { outv[3] = f4add(outv[3], W0); outv[4] = f4add(outv[4], W1); outv[5] = f4add(outv[5], W2); }
            }
        }

        float4* dst = (float4*)g_S2 + ((size_t)(b * RCHUNKS + chunk) * SLOTS) * (CC / 4) + q;
#pragma unroll
        for (int s = 0; s < SLOTS; s++)
            dst[(size_t)s * (CC / 4)] = outv[s];
    }
}

// ---------------------------------------------------------------------------
// K2: per-batch logits + route via composed W2. One block per batch, 256
// threads. Each thread strip-mines the 576 i-quads: sum 14 L2-hot chunk
// partials, fused float4-dot against W2 rows. Warp-shuffle + smem reduction
// -> logits(4) + argmax -> route.
// ---------------------------------------------------------------------------
__global__ __launch_bounds__(256) void logits_route_kernel(float* __restrict__ out_logits) {
    const int b   = blockIdx.x;
    const int tid = threadIdx.x;

    float4 acc = make_float4(0.f, 0.f, 0.f, 0.f);

    for (int q4 = tid; q4 < NQ; q4 += 256) {
        float4 s = make_float4(0.f, 0.f, 0.f, 0.f);
#pragma unroll
        for (int k = 0; k < RCHUNKS; k++) {
            const float4* src = (const float4*)g_S2
                              + (size_t)(b * RCHUNKS + k) * NQ + q4;
            s = f4add(s, __ldcg(src));
        }
        const float4* w2 = (const float4*)g_W2 + q4 * 4;  // rows i=4q4..4q4+3
        acc = f4fma(s.x, w2[0], acc);
        acc = f4fma(s.y, w2[1], acc);
        acc = f4fma(s.z, w2[2], acc);
        acc = f4fma(s.w, w2[3], acc);
    }

    // warp reduction
#pragma unroll
    for (int off = 16; off > 0; off >>= 1) {
        acc.x += __shfl_xor_sync(0xFFFFFFFFu, acc.x, off);
        acc.y += __shfl_xor_sync(0xFFFFFFFFu, acc.y, off);
        acc.z += __shfl_xor_sync(0xFFFFFFFFu, acc.z, off);
        acc.w += __shfl_xor_sync(0xFFFFFFFFu, acc.w, off);
    }

    __shared__ float4 wred[8];
    if ((tid & 31) == 0) wred[tid >> 5] = acc;
    __syncthreads();

    if (tid == 0) {
        float4 tot = wred[0];
#pragma unroll
        for (int wg = 1; wg < 8; wg++) tot = f4add(tot, wred[wg]);

        float l[ROUTES];
        l[0] = tot.x + g_C[0];
        l[1] = tot.y + g_C[1];
        l[2] = tot.z + g_C[2];
        l[3] = tot.w + g_C[3];

        float best = l[0];
        int br = 0;
#pragma unroll
        for (int r = 1; r < ROUTES; r++)
            if (l[r] > best) { best = l[r]; br = r; }   // first-max == argmax
        g_route[b] = br;

        out_logits[b * ROUTES + 0] = l[0];
        out_logits[b * ROUTES + 1] = l[1];
        out_logits[b * ROUTES + 2] = l[2];
        out_logits[b * ROUTES + 3] = l[3];
    }
}

// ---------------------------------------------------------------------------
// K3: routed channel-group gather. Block = (batch, 64-pixel tile),
// 128 threads x 8 independent float4 copies (double the per-warp MLP of the
// R11 config; same tiles, same coalescing).
// ---------------------------------------------------------------------------
__global__ __launch_bounds__(128) void gather_kernel(const float4* __restrict__ in4,
                                                     float4* __restrict__ out4) {
    const int b = blockIdx.x;
    const int r = g_route[b];
    const size_t base_pix = (size_t)b * (HH * WW) + (size_t)blockIdx.y * 64;
    const float4* src = in4 + base_pix * (CC / 4) + r * (RW / 4);
    float4* dst = out4 + base_pix * (RW / 4);

    const int t = threadIdx.x;
#pragma unroll
    for (int k = 0; k < 8; k++) {
        const int item = t + k * 128;      // 0..1023 = 64 pixels x 16 float4
        const int p = item >> 4;
        const int j = item & 15;
        dst[item] = src[(size_t)p * (CC / 4) + j];
    }
}

// ---------------------------------------------------------------------------
extern "C" void kernel_launch(void* const* d_in, const int* in_sizes, int n_in,
                              void* d_out, int out_size) {
    const float* in     = (const float*)d_in[0];
    const float* conv_w = (const float*)d_in[1];
    const float* conv_b = (const float*)d_in[2];
    const float* fc_w   = (const float*)d_in[3];
    const float* fc_b   = (const float*)d_in[4];

    float* out        = (float*)d_out;
    float* out_logits = out + (size_t)BB * HH * WW * RW;  // x first, then logits

    patch_w2_kernel<<<dim3(BB, RCHUNKS + 1), 256>>>(in, conv_w, conv_b, fc_w, fc_b);
    logits_route_kernel<<<BB, 256>>>(out_logits);
    gather_kernel<<<dim3(BB, HH * WW / 64), 128>>>((const float4*)in, (float4*)out);
}